// round 17
// baseline (speedup 1.0000x reference)
#include <cuda_runtime.h>
#include <cuda_fp16.h>

typedef unsigned long long u64;
typedef unsigned int u32;

#define B_   256
#define T_   512
#define NIN  512
#define H_   256
#define G3H  768
#define NC   101
#define CL   4
#define NBG  16
#define WROWS 192
#define WBYTES (WROWS * 512)
#define ABUF  8192
#define SMEM_GRU (WBYTES + 4 * ABUF)   // 131072: W + 2 groups x 2 stages

// ---- scratch ---------------------------------------------------------------
__device__ __half g_xg[(size_t)B_ * T_ * G3H];   // input gate proj, fp16
__device__ __half g_xh[(size_t)B_ * T_ * NIN];
__device__ __half g_wh[G3H * NIN];
__device__ float  g_hT[B_ * H_];

// ---- ptx helpers -----------------------------------------------------------
__device__ __forceinline__ void lds4(u32& r0, u32& r1, u32& r2, u32& r3, u32 a) {
    asm volatile("ldmatrix.sync.aligned.m8n8.x4.shared.b16 {%0,%1,%2,%3}, [%4];"
                 : "=r"(r0), "=r"(r1), "=r"(r2), "=r"(r3) : "r"(a));
}
__device__ __forceinline__ void lds2(u32& r0, u32& r1, u32 a) {
    asm volatile("ldmatrix.sync.aligned.m8n8.x2.shared.b16 {%0,%1}, [%2];"
                 : "=r"(r0), "=r"(r1) : "r"(a));
}
__device__ __forceinline__ void mma16816(float* c, const u32* a, const u32* b) {
    asm volatile("mma.sync.aligned.m16n8k16.row.col.f32.f16.f16.f32 "
                 "{%0,%1,%2,%3}, {%4,%5,%6,%7}, {%8,%9}, {%0,%1,%2,%3};"
                 : "+f"(c[0]), "+f"(c[1]), "+f"(c[2]), "+f"(c[3])
                 : "r"(a[0]), "r"(a[1]), "r"(a[2]), "r"(a[3]), "r"(b[0]), "r"(b[1]));
}
__device__ __forceinline__ u32 mapa_(u32 addr, u32 rank) {
    u32 r; asm("mapa.shared::cluster.u32 %0, %1, %2;" : "=r"(r) : "r"(addr), "r"(rank));
    return r;
}
__device__ __forceinline__ void stclu(u32 addr, u32 v) {
    asm volatile("st.shared::cluster.u32 [%0], %1;" :: "r"(addr), "r"(v) : "memory");
}
__device__ __forceinline__ void cluster_arrive() {
    asm volatile("barrier.cluster.arrive.aligned;" ::: "memory");
}
__device__ __forceinline__ void cluster_wait() {
    asm volatile("barrier.cluster.wait.aligned;" ::: "memory");
}
__device__ __forceinline__ u32 ctarank() {
    u32 r; asm("mov.u32 %0, %%cluster_ctarank;" : "=r"(r)); return r;
}
__device__ __forceinline__ int sw7(int chunk, int row) {
    return (chunk & 24) | ((chunk ^ (row & 7)) & 7);
}
__device__ __forceinline__ float tanh_ap(float x) {
    float y; asm("tanh.approx.f32 %0, %1;" : "=f"(y) : "f"(x)); return y;
}
__device__ __forceinline__ float sigm_ap(float x) {
    return fmaf(tanh_ap(0.5f * x), 0.5f, 0.5f);
}
__device__ __forceinline__ void cpa(u32 dst, const void* src) {
    asm volatile("cp.async.cg.shared.global [%0], [%1], 16;" :: "r"(dst), "l"(src) : "memory");
}
__device__ __forceinline__ void cpcommit() {
    asm volatile("cp.async.commit_group;" ::: "memory");
}
template<int N> __device__ __forceinline__ void cpwait() {
    asm volatile("cp.async.wait_group %0;" :: "n"(N) : "memory");
}

// ---- fp32 -> fp16 convert --------------------------------------------------
__global__ void cvt2h(const float* __restrict__ in, __half2* __restrict__ out, int n2) {
    for (int i = blockIdx.x * blockDim.x + threadIdx.x; i < n2; i += gridDim.x * blockDim.x) {
        float2 v = ((const float2*)in)[i];
        out[i] = __floats2half2_rn(v.x, v.y);
    }
}

// ===========================================================================
// Kernel A: fp16 HMMA GEMM, CTA tile 128x128, K-tile 32, 3-stage cp.async.
// 8 warps (4m x 2n), warp tile 32x64. Output fp16 (+fp32 bias).
// ===========================================================================
__global__ __launch_bounds__(256)
void hgemm(const __half* __restrict__ Ah, const __half* __restrict__ Wh,
           const float* __restrict__ bih) {
    __shared__ __align__(16) char hsm[3 * 8192 + 3 * 8192];
    const int tid = threadIdx.x;
    const int lane = tid & 31, warp = tid >> 5;
    const int wm = warp & 3, wn = warp >> 2;
    const size_t mBase = (size_t)blockIdx.y * 128;
    const int nBase = blockIdx.x * 128;

    const int lr = tid >> 2, lc = tid & 3;
    const uint4* aG0 = (const uint4*)(Ah + (mBase + lr) * NIN) + lc;
    const uint4* aG1 = aG0 + (64 * NIN) / 8;
    const uint4* bG0 = (const uint4*)(Wh + (size_t)(nBase + lr) * NIN) + lc;
    const uint4* bG1 = bG0 + (64 * NIN) / 8;
    const int stA = lr * 64 + ((lc ^ ((lr >> 1) & 3)) * 16);   // also for rows+64: +4096

    const u32 aSm = (u32)__cvta_generic_to_shared(hsm);
    const u32 bSm = aSm + 3 * 8192;

    const int rowA = wm * 32 + ((lane >> 3) & 1) * 8 + (lane & 7);
    const int loffA = rowA * 64 + (((lane >> 4) ^ ((rowA >> 1) & 3)) * 16);
    const int rowB = wn * 64 + (lane >> 4) * 8 + (lane & 7);
    const int loffB = rowB * 64 + ((((lane >> 3) & 1) ^ ((rowB >> 1) & 3)) * 16);

    float c[2][8][4];
    #pragma unroll
    for (int mi = 0; mi < 2; mi++)
        #pragma unroll
        for (int ni = 0; ni < 8; ni++)
            #pragma unroll
            for (int qq = 0; qq < 4; qq++) c[mi][ni][qq] = 0.f;

    #pragma unroll
    for (int p = 0; p < 2; p++) {
        const u32 da = aSm + p * 8192 + stA;
        const u32 db = bSm + p * 8192 + stA;
        cpa(da,        aG0 + p * 4);
        cpa(da + 4096, aG1 + p * 4);
        cpa(db,        bG0 + p * 4);
        cpa(db + 4096, bG1 + p * 4);
        cpcommit();
    }

    int slotc = 0, slotl = 2;
    for (int kt = 0; kt < 16; kt++) {
        cpwait<1>();
        __syncthreads();
        if (kt + 2 < 16) {
            const u32 da = aSm + slotl * 8192 + stA;
            const u32 db = bSm + slotl * 8192 + stA;
            cpa(da,        aG0 + (kt + 2) * 4);
            cpa(da + 4096, aG1 + (kt + 2) * 4);
            cpa(db,        bG0 + (kt + 2) * 4);
            cpa(db + 4096, bG1 + (kt + 2) * 4);
        }
        cpcommit();
        const u32 aB = aSm + slotc * 8192;
        const u32 bB = bSm + slotc * 8192;
        #pragma unroll
        for (int t = 0; t < 2; t++) {
            u32 aF[2][4], bF[4][4];
            lds4(aF[0][0], aF[0][1], aF[0][2], aF[0][3], aB + ((loffA) ^ (t << 5)));
            lds4(aF[1][0], aF[1][1], aF[1][2], aF[1][3], aB + ((loffA + 1024) ^ (t << 5)));
            #pragma unroll
            for (int i = 0; i < 4; i++)
                lds4(bF[i][0], bF[i][1], bF[i][2], bF[i][3],
                     bB + ((loffB + i * 1024) ^ (t << 5)));
            #pragma unroll
            for (int mi = 0; mi < 2; mi++)
                #pragma unroll
                for (int ni = 0; ni < 8; ni++)
                    mma16816(c[mi][ni], aF[mi], &bF[ni >> 1][(ni & 1) * 2]);
        }
        slotc = (slotc + 1 == 3) ? 0 : slotc + 1;
        slotl = (slotl + 1 == 3) ? 0 : slotl + 1;
    }

    const int er = lane >> 2, ec = (lane & 3) * 2;
    #pragma unroll
    for (int mi = 0; mi < 2; mi++) {
        const size_t m0 = mBase + wm * 32 + mi * 16 + er;
        #pragma unroll
        for (int ni = 0; ni < 8; ni++) {
            const int col = nBase + wn * 64 + ni * 8 + ec;
            const float2 bv = *(const float2*)&bih[col];
            __half2 o0 = __floats2half2_rn(c[mi][ni][0] + bv.x, c[mi][ni][1] + bv.y);
            __half2 o1 = __floats2half2_rn(c[mi][ni][2] + bv.x, c[mi][ni][3] + bv.y);
            *(u32*)(g_xg + m0 * G3H + col)       = *(u32*)&o0;
            *(u32*)(g_xg + (m0 + 8) * G3H + col) = *(u32*)&o1;
        }
    }
}

// ===========================================================================
// Kernel B: tensor-core GRU, TWO batch-groups per cluster sharing one
// barrier per step (tails overlap). 8 clusters x 4 CTAs, 32 batches each.
// W fragments in registers; h broadcast fp16 via DSMEM; state fp32 in regs.
// ===========================================================================
__global__ __launch_bounds__(256, 1) __cluster_dims__(CL, 1, 1)
void gru_mma(const float* __restrict__ Whh, const float* __restrict__ bhh) {
    extern __shared__ char sm[];
    char* WS = sm;                 // W staging (dead after prologue)
    char* AS = sm + WBYTES;        // [group(2)][stage(2)][8KB]

    const int tid = threadIdx.x;
    const int lane = tid & 31, warp = tid >> 5;
    const u32 q = ctarank();
    const int cidx = blockIdx.x >> 2;          // cluster 0..7
    const int b0A = (2 * cidx) * NBG;
    const int b0B = (2 * cidx + 1) * NBG;

    // ---- prologue: stage + convert + swizzle W slice ----
    for (int t = tid; t < WROWS * 32; t += 256) {
        int row = t >> 5, ch = t & 31;
        int jt = row / 24, rem = row - jt * 24;
        int g = rem >> 3, rr = rem & 7;
        int grow = g * 256 + (int)q * 64 + jt * 8 + rr;
        const float4* src = (const float4*)(Whh + (size_t)grow * H_ + ch * 8);
        float4 f0 = src[0], f1 = src[1];
        __half2 h0 = __floats2half2_rn(f0.x, f0.y), h1 = __floats2half2_rn(f0.z, f0.w);
        __half2 h2 = __floats2half2_rn(f1.x, f1.y), h3 = __floats2half2_rn(f1.z, f1.w);
        uint4 v = make_uint4(*(u32*)&h0, *(u32*)&h1, *(u32*)&h2, *(u32*)&h3);
        *(uint4*)(WS + row * 512 + sw7(ch, row) * 16) = v;
    }
    for (int t = tid; t < (4 * ABUF) / 16; t += 256)
        ((uint4*)AS)[t] = make_uint4(0, 0, 0, 0);
    __syncthreads();

    // ---- hoist W fragments into registers ----
    const u32 wsS = (u32)__cvta_generic_to_shared(WS);
    const int brow = warp * 24 + ((lane >> 4) & 1) * 8 + (lane & 7);
    const int bchl = (lane >> 3) & 1;
    const int nrow = warp * 24 + 16 + (lane & 7);
    u32 bR[16][2], bZ[16][2], bN[16][2];
    #pragma unroll
    for (int kc = 0; kc < 16; kc++) {
        const int cB = kc * 2 + bchl;
        u32 t0, t1, t2, t3;
        lds4(t0, t1, t2, t3, wsS + brow * 512 + sw7(cB, brow) * 16);
        bR[kc][0] = t0; bR[kc][1] = t1; bZ[kc][0] = t2; bZ[kc][1] = t3;
        lds2(bN[kc][0], bN[kc][1], wsS + nrow * 512 + sw7(cB, nrow) * 16);
    }

    // ---- per-thread constants ----
    const int jl = (lane & 3) * 2;
    const int jg = (int)q * 64 + warp * 8 + jl;
    const int m_ = lane >> 2;
    const float2 br = *(const float2*)&bhh[jg];
    const float2 bz = *(const float2*)&bhh[256 + jg];
    const float2 bq = *(const float2*)&bhh[512 + jg];

    const __half* xgA0 = g_xg + (size_t)(b0A + m_) * T_ * G3H + jg;
    const __half* xgA1 = g_xg + (size_t)(b0A + m_ + 8) * T_ * G3H + jg;
    const __half* xgB0 = g_xg + (size_t)(b0B + m_) * T_ * G3H + jg;
    const __half* xgB1 = g_xg + (size_t)(b0B + m_ + 8) * T_ * G3H + jg;

    const u32 asS = (u32)__cvta_generic_to_shared(AS);
    const int arow = ((lane >> 3) & 1) * 8 + (lane & 7);
    const int achl = (lane >> 4) & 1;

    const int chw = (int)q * 8 + warp;
    const u32 woff0 = m_ * 512 + sw7(chw, m_) * 16 + (lane & 3) * 4;
    const u32 woff1 = woff0 + 8 * 512;

    u32 asR[CL];
    #pragma unroll
    for (int r = 0; r < CL; r++) asR[r] = mapa_(asS, (u32)r);

    float hA[4] = {0.f, 0.f, 0.f, 0.f};
    float hB[4] = {0.f, 0.f, 0.f, 0.f};

    // step-0 xg prefetch (u32 = 2 halfs)
    u32 xA[6], xB[6];
    xA[0] = *(const u32*)xgA0;        xA[1] = *(const u32*)(xgA0 + 256);
    xA[2] = *(const u32*)(xgA0 + 512);
    xA[3] = *(const u32*)xgA1;        xA[4] = *(const u32*)(xgA1 + 256);
    xA[5] = *(const u32*)(xgA1 + 512);
    xB[0] = *(const u32*)xgB0;        xB[1] = *(const u32*)(xgB0 + 256);
    xB[2] = *(const u32*)(xgB0 + 512);
    xB[3] = *(const u32*)xgB1;        xB[4] = *(const u32*)(xgB1 + 256);
    xB[5] = *(const u32*)(xgB1 + 512);

    cluster_arrive(); cluster_wait();

    for (int s = 0; s < T_; s++) {
        const u32 stg = (u32)(s & 1) * ABUF;
        const u32 abA = asS + stg;                 // group A
        const u32 abB = asS + 2 * ABUF + stg;      // group B

        float crA[4] = {0,0,0,0}, czA[4] = {0,0,0,0}, cnA[4] = {0,0,0,0};
        float crB[4] = {0,0,0,0}, czB[4] = {0,0,0,0}, cnB[4] = {0,0,0,0};

        #pragma unroll
        for (int kc = 0; kc < 16; kc++) {
            const int cA = kc * 2 + achl;
            const u32 off = arow * 512 + sw7(cA, arow) * 16;
            u32 ah[4];
            lds4(ah[0], ah[1], ah[2], ah[3], abA + off);
            mma16816(crA, ah, bR[kc]);
            mma16816(czA, ah, bZ[kc]);
            mma16816(cnA, ah, bN[kc]);
        }
        #pragma unroll
        for (int kc = 0; kc < 16; kc++) {
            const int cA = kc * 2 + achl;
            const u32 off = arow * 512 + sw7(cA, arow) * 16;
            u32 ah[4];
            lds4(ah[0], ah[1], ah[2], ah[3], abB + off);
            mma16816(crB, ah, bR[kc]);
            mma16816(czB, ah, bZ[kc]);
            mma16816(cnB, ah, bN[kc]);
        }

        const u32 nbuf = (u32)((s + 1) & 1) * ABUF;
        float hvA[4], hvB[4];
        {
            const float brv[4] = {br.x, br.y, br.x, br.y};
            const float bzv[4] = {bz.x, bz.y, bz.x, bz.y};
            const float bnv[4] = {bq.x, bq.y, bq.x, bq.y};
            float2 xfA[6], xfB[6];
            #pragma unroll
            for (int i = 0; i < 6; i++) {
                xfA[i] = __half22float2(*(__half2*)&xA[i]);
                xfB[i] = __half22float2(*(__half2*)&xB[i]);
            }
            const float xrA[4] = {xfA[0].x, xfA[0].y, xfA[3].x, xfA[3].y};
            const float xzA[4] = {xfA[1].x, xfA[1].y, xfA[4].x, xfA[4].y};
            const float xnA[4] = {xfA[2].x, xfA[2].y, xfA[5].x, xfA[5].y};
            const float xrB[4] = {xfB[0].x, xfB[0].y, xfB[3].x, xfB[3].y};
            const float xzB[4] = {xfB[1].x, xfB[1].y, xfB[4].x, xfB[4].y};
            const float xnB[4] = {xfB[2].x, xfB[2].y, xfB[5].x, xfB[5].y};
            #pragma unroll
            for (int i = 0; i < 4; i++) {
                float rr = sigm_ap(xrA[i] + crA[i] + brv[i]);
                float zz = sigm_ap(xzA[i] + czA[i] + bzv[i]);
                float nn = tanh_ap(xnA[i] + rr * (cnA[i] + bnv[i]));
                hvA[i] = (1.f - zz) * nn + zz * hA[i];
                hA[i] = hvA[i];
            }
            // group A stores fire while group B gates compute
            __half2 a0 = __floats2half2_rn(hvA[0], hvA[1]);
            __half2 a1 = __floats2half2_rn(hvA[2], hvA[3]);
            #pragma unroll
            for (int r = 0; r < CL; r++) {
                const u32 base = asR[r] + nbuf;
                stclu(base + woff0, *(u32*)&a0);
                stclu(base + woff1, *(u32*)&a1);
            }
            #pragma unroll
            for (int i = 0; i < 4; i++) {
                float rr = sigm_ap(xrB[i] + crB[i] + brv[i]);
                float zz = sigm_ap(xzB[i] + czB[i] + bzv[i]);
                float nn = tanh_ap(xnB[i] + rr * (cnB[i] + bnv[i]));
                hvB[i] = (1.f - zz) * nn + zz * hB[i];
                hB[i] = hvB[i];
            }
            __half2 b0 = __floats2half2_rn(hvB[0], hvB[1]);
            __half2 b1 = __floats2half2_rn(hvB[2], hvB[3]);
            #pragma unroll
            for (int r = 0; r < CL; r++) {
                const u32 base = asR[r] + 2 * ABUF + nbuf;
                stclu(base + woff0, *(u32*)&b0);
                stclu(base + woff1, *(u32*)&b1);
            }
        }
        cluster_arrive();

        if (s < T_ - 1) {
            const size_t o = (size_t)(s + 1) * G3H;
            xA[0] = *(const u32*)(xgA0 + o);        xA[1] = *(const u32*)(xgA0 + o + 256);
            xA[2] = *(const u32*)(xgA0 + o + 512);
            xA[3] = *(const u32*)(xgA1 + o);        xA[4] = *(const u32*)(xgA1 + o + 256);
            xA[5] = *(const u32*)(xgA1 + o + 512);
            xB[0] = *(const u32*)(xgB0 + o);        xB[1] = *(const u32*)(xgB0 + o + 256);
            xB[2] = *(const u32*)(xgB0 + o + 512);
            xB[3] = *(const u32*)(xgB1 + o);        xB[4] = *(const u32*)(xgB1 + o + 256);
            xB[5] = *(const u32*)(xgB1 + o + 512);
        } else {
            *(float2*)(g_hT + (size_t)(b0A + m_) * H_ + jg)     = make_float2(hvA[0], hvA[1]);
            *(float2*)(g_hT + (size_t)(b0A + m_ + 8) * H_ + jg) = make_float2(hvA[2], hvA[3]);
            *(float2*)(g_hT + (size_t)(b0B + m_) * H_ + jg)     = make_float2(hvB[0], hvB[1]);
            *(float2*)(g_hT + (size_t)(b0B + m_ + 8) * H_ + jg) = make_float2(hvB[2], hvB[3]);
        }
        cluster_wait();
    }
}

// ===========================================================================
// Kernel C: out[b,c] = hT[b] . fc_w[c] + fc_b[c]
// ===========================================================================
#define NBF 8
__global__ void fc_kernel(const float* __restrict__ fcw,
                          const float* __restrict__ fcb,
                          float* __restrict__ out) {
    __shared__ float hs[NBF][H_];
    const int b0 = blockIdx.x * NBF;
    for (int i = threadIdx.x; i < NBF * H_; i += blockDim.x)
        hs[i >> 8][i & 255] = g_hT[(size_t)b0 * H_ + i];
    __syncthreads();
    const int c = threadIdx.x;
    if (c < NC) {
        float acc[NBF];
        #pragma unroll
        for (int b = 0; b < NBF; b++) acc[b] = fcb[c];
        const float* w = fcw + (size_t)c * H_;
        #pragma unroll 4
        for (int k = 0; k < H_; k++) {
            float wv = w[k];
            #pragma unroll
            for (int b = 0; b < NBF; b++) acc[b] = fmaf(hs[b][k], wv, acc[b]);
        }
        #pragma unroll
        for (int b = 0; b < NBF; b++) out[(size_t)(b0 + b) * NC + c] = acc[b];
    }
}

// ===========================================================================
extern "C" void kernel_launch(void* const* d_in, const int* in_sizes, int n_in,
                              void* d_out, int out_size) {
    const float* x   = (const float*)d_in[0];
    const float* Wih = (const float*)d_in[1];
    const float* Whh = (const float*)d_in[2];
    const float* bih = (const float*)d_in[3];
    const float* bhh = (const float*)d_in[4];
    const float* fcw = (const float*)d_in[5];
    const float* fcb = (const float*)d_in[6];
    float* out = (float*)d_out;

    cudaFuncSetAttribute(gru_mma,
                         cudaFuncAttributeMaxDynamicSharedMemorySize, SMEM_GRU);

    __half2* xh2; cudaGetSymbolAddress((void**)&xh2, g_xh);
    __half2* wh2; cudaGetSymbolAddress((void**)&wh2, g_wh);

    cvt2h<<<2048, 256>>>(x, xh2, (B_ * T_ * NIN) / 2);
    cvt2h<<<256, 256>>>(Wih, wh2, (G3H * NIN) / 2);

    __half* xh; cudaGetSymbolAddress((void**)&xh, g_xh);
    __half* wh; cudaGetSymbolAddress((void**)&wh, g_wh);
    dim3 g1(G3H / 128, (B_ * T_) / 128);
    hgemm<<<g1, 256>>>(xh, wh, bih);

    gru_mma<<<8 * CL, 256, SMEM_GRU>>>(Whh, bhh);
    fc_kernel<<<B_ / NBF, 128>>>(fcw, fcb, out);
}